// round 16
// baseline (speedup 1.0000x reference)
#include <cuda_runtime.h>
#include <cuda_bf16.h>
#include <math.h>
#include <stdint.h>

// ---------------------------------------------------------------------------
// Problem constants (Mamba2 block)
// ---------------------------------------------------------------------------
#define BATCH     2
#define SEQLEN    4096
#define DMODEL    1024
#define DSTATE    128
#define DCONV     4
#define HEADDIM   64
#define DINNER    2048
#define NHEADS    32
#define CONVDIM   2304              // DINNER + 2*DSTATE
#define DINPROJ   4384              // 2*DINNER + 2*DSTATE + NHEADS
#define ROWS      (BATCH*SEQLEN)    // 8192
#define DTCOL     (2*DINNER + 2*DSTATE)   // 4352

#define T_CH      64
#define NCHUNK    (SEQLEN / T_CH)   // 64

// Scratch (allocation-free rule: __device__ globals)
__device__ float g_zxbcdt[(size_t)ROWS * DINPROJ];
__device__ float g_conv  [(size_t)ROWS * CONVDIM];   // tf32-rounded conv+silu
__device__ float g_y     [(size_t)ROWS * DINNER];
__device__ float g_xtf   [(size_t)ROWS * DMODEL];
__device__ float g_w1tf  [(size_t)DMODEL * DINPROJ];
__device__ float g_w2tf  [(size_t)DINNER * DMODEL];

__device__ __forceinline__ uint32_t f2tf32(float f) {
    uint32_t r;
    asm("cvt.rna.tf32.f32 %0, %1;" : "=r"(r) : "f"(f));
    return r;
}
__device__ __forceinline__ float tfr(float f) {
    return __uint_as_float(f2tf32(f));
}
__device__ __forceinline__ uint32_t smem_addr(const void* p) {
    return (uint32_t)__cvta_generic_to_shared(p);
}
__device__ __forceinline__ void cp16(uint32_t dst, const void* src, int sz) {
    asm volatile("cp.async.cg.shared.global [%0], [%1], 16, %2;"
                 :: "r"(dst), "l"(src), "r"(sz) : "memory");
}
__device__ __forceinline__ void cp4(uint32_t dst, const void* src) {
    asm volatile("cp.async.ca.shared.global [%0], [%1], 4;"
                 :: "r"(dst), "l"(src) : "memory");
}
#define CP_COMMIT() asm volatile("cp.async.commit_group;" ::: "memory")
#define CP_WAIT(n)  asm volatile("cp.async.wait_group %0;" :: "n"(n) : "memory")

#define MMA_TF32(acc, a0, a1, a2, a3, b0, b1)                               \
    asm volatile(                                                           \
        "mma.sync.aligned.m16n8k8.row.col.f32.tf32.tf32.f32 "               \
        "{%0,%1,%2,%3}, {%4,%5,%6,%7}, {%8,%9}, {%0,%1,%2,%3};"             \
        : "+f"((acc)[0]), "+f"((acc)[1]), "+f"((acc)[2]), "+f"((acc)[3])    \
        : "r"(a0), "r"(a1), "r"(a2), "r"(a3), "r"(b0), "r"(b1))

// ---------------------------------------------------------------------------
// Elementwise tf32 rounding pre-pass
// ---------------------------------------------------------------------------
__global__ void cvt_tf32_kernel(const float* __restrict__ in,
                                float* __restrict__ out, long n4)
{
    long i = (long)blockIdx.x * blockDim.x + threadIdx.x;
    if (i >= n4) return;
    float4 v = ((const float4*)in)[i];
    float4 o = make_float4(tfr(v.x), tfr(v.y), tfr(v.z), tfr(v.w));
    ((float4*)out)[i] = o;
}

// ---------------------------------------------------------------------------
// TF32 mma.sync GEMM, 3-stage cp.async pipeline (128x128 tile, 2 CTA/SM).
// C[r*ldC + c] = sum_k A[r*K + k] * B[k*ldB + c], c < Nb (guarded).
// ---------------------------------------------------------------------------
#define GSTAGES 3
#define ASTR 36
#define BSTR 136
#define STAGE_WORDS (128*ASTR + 32*BSTR)
#define GEMM_SMEM   (GSTAGES * STAGE_WORDS * 4)

__global__ __launch_bounds__(256, 2)
void tf32_gemm_kernel(const float* __restrict__ A, const float* __restrict__ B,
                      float* __restrict__ C, int M, int Nb, int K,
                      int ldB, int ldC)
{
    extern __shared__ uint32_t smem[];

    const int tid   = threadIdx.x;
    const int warp  = tid >> 5;
    const int lane  = tid & 31;
    const int g     = lane >> 2;
    const int t4    = lane & 3;
    const int warpM = warp >> 2;
    const int warpN = warp & 3;
    const int rowC  = blockIdx.y * 128;
    const int colC  = blockIdx.x * 128;
    const int NC    = K / 32;

    auto stage_cp = [&](int chunk, int slot) {
        uint32_t* As = smem + slot * STAGE_WORDS;
        uint32_t* Bs = As + 128 * ASTR;
        const int k0 = chunk * 32;
        #pragma unroll
        for (int p = 0; p < 4; p++) {
            int i = p * 256 + tid;
            int m = i >> 3, kq = i & 7;
            cp16(smem_addr(As + m * ASTR + kq * 4),
                 A + (size_t)(rowC + m) * K + k0 + kq * 4, 16);
        }
        #pragma unroll
        for (int p = 0; p < 4; p++) {
            int i = p * 256 + tid;
            int kl = i >> 5, nq = i & 31;
            int gcol = colC + nq * 4;
            int ok = (gcol < Nb);
            cp16(smem_addr(Bs + kl * BSTR + nq * 4),
                 B + (size_t)(k0 + kl) * ldB + (ok ? gcol : 0), ok ? 16 : 0);
        }
    };

    float acc[4][4][4];
    #pragma unroll
    for (int mi = 0; mi < 4; mi++)
        #pragma unroll
        for (int ni = 0; ni < 4; ni++)
            #pragma unroll
            for (int r = 0; r < 4; r++) acc[mi][ni][r] = 0.f;

    stage_cp(0, 0); CP_COMMIT();
    stage_cp(1, 1); CP_COMMIT();

    for (int i = 0; i < NC; i++) {
        if (i < NC - 1) CP_WAIT(1); else CP_WAIT(0);
        __syncthreads();
        if (i + 2 < NC) { stage_cp(i + 2, (i + 2) % GSTAGES); CP_COMMIT(); }

        const uint32_t* As = smem + (i % GSTAGES) * STAGE_WORDS;
        const uint32_t* Bs = As + 128 * ASTR;

        #pragma unroll
        for (int ks = 0; ks < 4; ks++) {
            const int kk = ks * 8;
            uint32_t af[4][4];
            #pragma unroll
            for (int mi = 0; mi < 4; mi++) {
                int m = warpM * 64 + mi * 16;
                af[mi][0] = As[(m + g)     * ASTR + kk + t4];
                af[mi][1] = As[(m + g + 8) * ASTR + kk + t4];
                af[mi][2] = As[(m + g)     * ASTR + kk + t4 + 4];
                af[mi][3] = As[(m + g + 8) * ASTR + kk + t4 + 4];
            }
            uint32_t bf[4][2];
            #pragma unroll
            for (int ni = 0; ni < 4; ni++) {
                int n = warpN * 32 + ni * 8 + g;
                bf[ni][0] = Bs[(kk + t4)     * BSTR + n];
                bf[ni][1] = Bs[(kk + t4 + 4) * BSTR + n];
            }
            #pragma unroll
            for (int mi = 0; mi < 4; mi++)
                #pragma unroll
                for (int ni = 0; ni < 4; ni++)
                    MMA_TF32(acc[mi][ni], af[mi][0], af[mi][1], af[mi][2],
                             af[mi][3], bf[ni][0], bf[ni][1]);
        }
    }

    #pragma unroll
    for (int mi = 0; mi < 4; mi++) {
        int r0 = rowC + warpM * 64 + mi * 16 + g;
        #pragma unroll
        for (int ni = 0; ni < 4; ni++) {
            int cc = colC + warpN * 32 + ni * 8 + t4 * 2;
            if (cc < Nb) {
                *(float2*)(C + (size_t)r0 * ldC + cc)       =
                    make_float2(acc[mi][ni][0], acc[mi][ni][1]);
                *(float2*)(C + (size_t)(r0 + 8) * ldC + cc) =
                    make_float2(acc[mi][ni][2], acc[mi][ni][3]);
            }
        }
    }
}

// ---------------------------------------------------------------------------
// Causal depthwise conv1d (K=4) + SiLU, sliding-window, 8 timesteps/thread.
// ---------------------------------------------------------------------------
__global__ __launch_bounds__(256)
void conv_silu_kernel(const float* __restrict__ zxbcdt,
                      const float* __restrict__ conv_w,
                      const float* __restrict__ conv_b,
                      float* __restrict__ out)
{
    const int  c  = blockIdx.x * 256 + threadIdx.x;
    const long r0 = (long)blockIdx.y * 8;
    const int  l0 = (int)(r0 & (SEQLEN - 1));

    const float w0 = conv_w[0 * CONVDIM + c];
    const float w1 = conv_w[1 * CONVDIM + c];
    const float w2 = conv_w[2 * CONVDIM + c];
    const float w3 = conv_w[3 * CONVDIM + c];
    const float bias = conv_b[c];

    const float* base = zxbcdt + r0 * DINPROJ + DINNER + c;
    float xm3 = 0.f, xm2 = 0.f, xm1 = 0.f;
    if (l0 > 0) {
        xm3 = base[-3 * (long)DINPROJ];
        xm2 = base[-2 * (long)DINPROJ];
        xm1 = base[-1 * (long)DINPROJ];
    }
    float* orow = out + r0 * CONVDIM + c;
    #pragma unroll
    for (int i = 0; i < 8; i++) {
        float x0 = base[(long)i * DINPROJ];
        float acc = bias + w0 * x0 + w1 * xm1 + w2 * xm2 + w3 * xm3;
        float s = acc / (1.f + __expf(-acc));
        orow[(long)i * CONVDIM] = tfr(s);
        xm3 = xm2; xm2 = xm1; xm1 = x0;
    }
}

// ---------------------------------------------------------------------------
// FUSED chunked scan (one persistent CTA per (b,h); state in registers).
// ---------------------------------------------------------------------------
#define SC_STG   (8448 + 8448 + 4352 + 64)          // 21312 words per stage
#define SC_WORDS (2*SC_STG + 8448 + 4352 + 4*64 + 8)
#define SC_SMEM  (SC_WORDS * 4)                      // 222,752 B

__global__ __launch_bounds__(256, 1)
void fused_scan_kernel(const float* __restrict__ convout,
                       const float* __restrict__ zxbcdt,
                       const float* __restrict__ dt_bias,
                       const float* __restrict__ A_log,
                       const float* __restrict__ Dparam,
                       float* __restrict__ y)
{
    extern __shared__ float sm[];

    const int bh  = blockIdx.x;
    const int b   = bh >> 5;
    const int h   = bh & 31;
    const long rb = (long)b * SEQLEN;
    const int tid  = threadIdx.x;
    const int warp = tid >> 5;
    const int lane = tid & 31;
    const int g    = lane >> 2;
    const int t4   = lane & 3;
    const int wM   = warp >> 2;
    const int wN   = warp & 3;

    const float A   = -__expf(A_log[h]);
    const float Dh  = Dparam[h];
    const float dtb = dt_bias[h];

    float* Ss   = sm + 2 * SC_STG;       // state [p][n], stride 132
    float* Ms   = Ss + 8448;             // masked gram [t][s], stride 68
    float* wrow = Ms + 4352;
    float* wcol = wrow + 64;
    float* swS  = wcol + 64;
    float* set  = swS + 64;
    float* scd  = set + 64;

    auto stage = [&](int k, int s) {
        float* Bs  = sm + s * SC_STG;
        float* Cs  = Bs + 8448;
        float* Xs  = Cs + 8448;
        float* dtr = Xs + 4352;
        const long r0 = rb + (long)k * T_CH;
        #pragma unroll
        for (int j = 0; j < 8; j++) {
            int idx = j * 256 + tid;
            int t = idx >> 5, q = idx & 31;
            const float* row = convout + (r0 + t) * CONVDIM;
            cp16(smem_addr(Bs + t * 132 + q * 4), row + DINNER + q * 4, 16);
            cp16(smem_addr(Cs + t * 132 + q * 4), row + DINNER + DSTATE + q * 4, 16);
        }
        #pragma unroll
        for (int j = 0; j < 4; j++) {
            int idx = j * 256 + tid;
            int t = idx >> 4, q = idx & 15;
            cp16(smem_addr(Xs + t * 68 + q * 4),
                 convout + (r0 + t) * CONVDIM + h * HEADDIM + q * 4, 16);
        }
        if (tid < 64)
            cp4(smem_addr(dtr + tid), zxbcdt + (r0 + tid) * DINPROJ + DTCOL + h);
    };

    float stacc[2][4][4];
    #pragma unroll
    for (int mi = 0; mi < 2; mi++)
        #pragma unroll
        for (int ni = 0; ni < 4; ni++)
            #pragma unroll
            for (int r = 0; r < 4; r++) stacc[mi][ni][r] = 0.f;

    stage(0, 0); CP_COMMIT();

    for (int k = 0; k < NCHUNK; k++) {
        const int s = k & 1;
        if (k + 1 < NCHUNK) { stage(k + 1, s ^ 1); CP_COMMIT(); }

        float* Bs  = sm + s * SC_STG;
        float* Cs  = Bs + 8448;
        float* Xs  = Cs + 8448;
        float* dtr = Xs + 4352;
        float* Xw  = Cs;                 // alias: valid after last Cs read
        const long r0 = rb + (long)k * T_CH;

        // ---- spill state -> Ss (tf32-rounded operand)
        #pragma unroll
        for (int mi = 0; mi < 2; mi++) {
            #pragma unroll
            for (int ni = 0; ni < 4; ni++) {
                int pb = wM * 32 + mi * 16;
                int nb = wN * 32 + ni * 8 + 2 * t4;
                Ss[(pb + g)     * 132 + nb]     = tfr(stacc[mi][ni][0]);
                Ss[(pb + g)     * 132 + nb + 1] = tfr(stacc[mi][ni][1]);
                Ss[(pb + g + 8) * 132 + nb]     = tfr(stacc[mi][ni][2]);
                Ss[(pb + g + 8) * 132 + nb + 1] = tfr(stacc[mi][ni][3]);
            }
        }

        if (k + 1 < NCHUNK) CP_WAIT(1); else CP_WAIT(0);
        __syncthreads();                 // stage k + Ss visible

        // ---- dt softplus + warp-shuffle cumsum + weights (warp 0)
        if (warp == 0) {
            float rv0 = dtr[lane] + dtb;
            float rv1 = dtr[lane + 32] + dtb;
            float d0 = (rv0 > 20.f) ? rv0 : log1pf(__expf(rv0));
            float d1 = (rv1 > 20.f) ? rv1 : log1pf(__expf(rv1));
            float v0 = d0, v1 = d1;
            #pragma unroll
            for (int off = 1; off < 32; off <<= 1) {
                float u0 = __shfl_up_sync(0xffffffffu, v0, off);
                float u1 = __shfl_up_sync(0xffffffffu, v1, off);
                if (lane >= off) { v0 += u0; v1 += u1; }
            }
            float tot0 = __shfl_sync(0xffffffffu, v0, 31);
            v1 += tot0;
            float ST   = __shfl_sync(0xffffffffu, v1, 31);
            float Smid = tot0;
            wrow[lane]      = __expf(A * (v0 - Smid));
            wrow[lane + 32] = __expf(A * (v1 - Smid));
            wcol[lane]      = d0 * __expf(-A * (v0 - Smid));
            wcol[lane + 32] = d1 * __expf(-A * (v1 - Smid));
            swS[lane]       = d0 * __expf(A * (ST - v0));
            swS[lane + 32]  = d1 * __expf(A * (ST - v1));
            set[lane]       = __expf(A * v0);
            set[lane + 32]  = __expf(A * v1);
            if (lane == 0) scd[0] = __expf(A * ST);
        }
        __syncthreads();
        const float cd = scd[0];

        // ---- merged: accs = C.S0^T and accg = C.B^T (shared af, K = 128)
        float accs[2][2][4], accg[2][2][4];
        #pragma unroll
        for (int mi = 0; mi < 2; mi++)
            #pragma unroll
            for (int ni = 0; ni < 2; ni++)
                #pragma unroll
                for (int r = 0; r < 4; r++) { accs[mi][ni][r] = 0.f; accg[mi][ni][r] = 0.f; }

        #pragma unroll
        for (int ks = 0; ks < 16; ks++) {
            const int kk = ks * 8;
            uint32_t af[2][4], bfS[2][2], bfB[2][2];
            #pragma unroll
            for (int mi = 0; mi < 2; mi++) {
                int m = wM * 32 + mi * 16;
                af[mi][0] = __float_as_uint(Cs[(m + g)     * 132 + kk + t4]);
                af[mi][1] = __float_as_uint(Cs[(m + g + 8) * 132 + kk + t4]);
                af[mi][2] = __float_as_uint(Cs[(m + g)     * 132 + kk + t4 + 4]);
                af[mi][3] = __float_as_uint(Cs[(m + g + 8) * 132 + kk + t4 + 4]);
            }
            #pragma unroll
            for (int ni = 0; ni < 2; ni++) {
                int p = wN * 16 + ni * 8 + g;
                bfS[ni][0] = __float_as_uint(Ss[p * 132 + kk + t4]);
                bfS[ni][1] = __float_as_uint(Ss[p * 132 + kk + t4 + 4]);
                bfB[ni][0] = __float_as_uint(Bs[p * 132 + kk + t4]);
                bfB[ni][1] = __float_as_uint(Bs[p * 132 + kk + t4 + 4]);
            }
            #pragma unroll
            for (int mi = 0; mi < 2; mi++)
                #pragma unroll
                for (int ni = 0; ni < 2; ni++) {
                    MMA_TF32(accs[mi][ni], af[mi][0], af[mi][1], af[mi][2],
                             af[mi][3], bfS[ni][0], bfS[ni][1]);
                    MMA_TF32(accg[mi][ni], af[mi][0], af[mi][1], af[mi][2],
                             af[mi][3], bfB[ni][0], bfB[ni][1]);
                }
        }
        __syncthreads();                 // all Cs/Ss reads done

        // ---- mask -> Ms; Xw[p][t] = swS_t * x[t][p]
        #pragma unroll
        for (int mi = 0; mi < 2; mi++) {
            #pragma unroll
            for (int ni = 0; ni < 2; ni++) {
                int tb = wM * 32 + mi * 16;
                int sb = wN * 16 + ni * 8 + 2 * t4;
                #pragma unroll
                for (int r = 0; r < 4; r++) {
                    int tt = tb + g + ((r >= 2) ? 8 : 0);
                    int ss = sb + (r & 1);
                    float w = (ss <= tt) ? wrow[tt] * wcol[ss] : 0.f;
                    Ms[tt * 68 + ss] = tfr(accg[mi][ni][r] * w);
                }
            }
        }
        #pragma unroll
        for (int j = 0; j < 16; j++) {
            int idx = j * 256 + tid;
            int p = idx >> 6, t = idx & 63;
            Xw[p * 68 + t] = tfr(swS[t] * Xs[t * 68 + p]);
        }
        __syncthreads();                 // Ms + Xw ready

        // ---- acc_y[t][p] = M . X (K = 64; reuse accg)
        #pragma unroll
        for (int mi = 0; mi < 2; mi++)
            #pragma unroll
            for (int ni = 0; ni < 2; ni++)
                #pragma unroll
                for (int r = 0; r < 4; r++) accg[mi][ni][r] = 0.f;

        #pragma unroll
        for (int ks = 0; ks < 8; ks++) {
            const int kk = ks * 8;
            uint32_t af[2][4], bf[2][2];
            #pragma unroll
            for (int mi = 0; mi < 2; mi++) {
                int m = wM * 32 + mi * 16;
                af[mi][0] = __float_as_uint(Ms[(m + g)     * 68 + kk + t4]);
                af[mi][1] = __float_as_uint(Ms[(m + g + 8) * 68 + kk + t4]);
                af[mi][2] = __float_as_uint(Ms[(m + g)     * 68 + kk + t4 + 4]);
                af[mi][3] = __float_as_uint(Ms[(m + g + 8) * 68 + kk + t4 + 4]);
            }
            #pragma unroll
            for (int ni = 0; ni < 2; ni++) {
                int p = wN * 16 + ni * 8 + g;
                bf[ni][0] = __float_as_uint(Xs[(kk + t4)     * 68 + p]);
                bf[ni][1] = __float_as_uint(Xs[(kk + t4 + 4) * 68 + p]);
            }
            #pragma unroll
            for (int mi = 0; mi < 2; mi++)
                #pragma unroll
                for (int ni = 0; ni < 2; ni++)
                    MMA_TF32(accg[mi][ni], af[mi][0], af[mi][1], af[mi][2],
                             af[mi][3], bf[ni][0], bf[ni][1]);
        }

        // ---- epilogue: y = Y_intra + et*(C.S0) + D*x (single write)
        #pragma unroll
        for (int mi = 0; mi < 2; mi++) {
            #pragma unroll
            for (int ni = 0; ni < 2; ni++) {
                int tb = wM * 32 + mi * 16;
                int pb = wN * 16 + ni * 8 + 2 * t4;
                int t0 = tb + g, t1 = tb + g + 8;
                float e0 = set[t0], e1 = set[t1];
                float2 o0 = make_float2(
                    accg[mi][ni][0] + e0 * accs[mi][ni][0] + Dh * Xs[t0 * 68 + pb],
                    accg[mi][ni][1] + e0 * accs[mi][ni][1] + Dh * Xs[t0 * 68 + pb + 1]);
                float2 o1 = make_float2(
                    accg[mi][ni][2] + e1 * accs[mi][ni][2] + Dh * Xs[t1 * 68 + pb],
                    accg[mi][ni][3] + e1 * accs[mi][ni][3] + Dh * Xs[t1 * 68 + pb + 1]);
                *(float2*)(y + (r0 + t0) * DINNER + h * HEADDIM + pb) = o0;
                *(float2*)(y + (r0 + t1) * DINNER + h * HEADDIM + pb) = o1;
            }
        }

        // ---- state update: stacc = cd*stacc + Xw . B (K = 64)
        #pragma unroll
        for (int mi = 0; mi < 2; mi++)
            #pragma unroll
            for (int ni = 0; ni < 4; ni++)
                #pragma unroll
                for (int r = 0; r < 4; r++) stacc[mi][ni][r] *= cd;

        #pragma unroll
        for (int ks = 0; ks < 8; ks++) {
            const int kk = ks * 8;
            uint32_t af[2][4], bf[4][2];
            #pragma unroll
            for (int mi = 0; mi < 2; mi++) {
                int p = wM * 32 + mi * 16;
                af[mi][0] = __float_as_uint(Xw[(p + g)     * 68 + kk + t4]);
                af[mi][1] = __float_as_uint(Xw[(p + g + 8) * 68 + kk + t4]);
                af[mi][2] = __float_as_uint(Xw[(p + g)     * 68 + kk + t4 + 4]);
                af[mi][3] = __float_as_uint(Xw[(p + g + 8) * 68 + kk + t4 + 4]);
            }
            #pragma unroll
            for (int ni = 0; ni < 4; ni++) {
                int n = wN * 32 + ni * 8 + g;
                bf[ni][0] = __float_as_uint(Bs[(kk + t4)     * 132 + n]);
                bf[ni][1] = __float_as_uint(Bs[(kk + t4 + 4) * 132 + n]);
            }
            #pragma unroll
            for (int mi = 0; mi < 2; mi++)
                #pragma unroll
                for (int ni = 0; ni < 4; ni++)
                    MMA_TF32(stacc[mi][ni], af[mi][0], af[mi][1], af[mi][2],
                             af[mi][3], bf[ni][0], bf[ni][1]);
        }
        __syncthreads();   // buf s reads done before re-stage
    }
}

// ---------------------------------------------------------------------------
// Gated RMSNorm in place on y; output tf32-rounded.
// ---------------------------------------------------------------------------
__global__ __launch_bounds__(256)
void gated_rmsnorm_kernel(float* __restrict__ y,
                          const float* __restrict__ zxbcdt,
                          const float* __restrict__ norm_w)
{
    long r = blockIdx.x;
    int tid = threadIdx.x;
    float* yr = y + r * DINNER;
    const float* zr = zxbcdt + r * DINPROJ;

    float vals[8];
    float ss = 0.f;
    #pragma unroll
    for (int i = 0; i < 8; i++) {
        int c = tid + i * 256;
        float z  = zr[c];
        float gv = yr[c] * (z / (1.f + __expf(-z)));
        vals[i] = gv;
        ss = fmaf(gv, gv, ss);
    }

    __shared__ float sred[256];
    sred[tid] = ss;
    __syncthreads();
    #pragma unroll
    for (int off = 128; off > 0; off >>= 1) {
        if (tid < off) sred[tid] += sred[tid + off];
        __syncthreads();
    }
    float scale = rsqrtf(sred[0] / (float)DINNER + 1e-5f);

    #pragma unroll
    for (int i = 0; i < 8; i++) {
        int c = tid + i * 256;
        yr[c] = tfr(vals[i] * scale * norm_w[c]);
    }
}

// ---------------------------------------------------------------------------
// Launch. Inputs: x, in_proj_w, conv_w, conv_b, norm_w, out_proj_w,
//                 dt_bias, A_log, D
// Stream overlap v3: conv + fused scan run on a HIGH-PRIORITY stream so the
// work distributor places their CTAs ahead of the z-GEMM's (which back-fills
// the ~84 SMs the scan leaves idle).
// ---------------------------------------------------------------------------
extern "C" void kernel_launch(void* const* d_in, const int* in_sizes, int n_in,
                              void* d_out, int out_size)
{
    const float* x          = (const float*)d_in[0];
    const float* in_proj_w  = (const float*)d_in[1];
    const float* conv_w     = (const float*)d_in[2];
    const float* conv_b     = (const float*)d_in[3];
    const float* norm_w     = (const float*)d_in[4];
    const float* out_proj_w = (const float*)d_in[5];
    const float* dt_bias    = (const float*)d_in[6];
    const float* A_log      = (const float*)d_in[7];
    const float* Dparam     = (const float*)d_in[8];
    float* out = (float*)d_out;

    float *zxbcdt, *convbuf, *ybuf, *xtf, *w1tf, *w2tf;
    cudaGetSymbolAddress((void**)&zxbcdt,  g_zxbcdt);
    cudaGetSymbolAddress((void**)&convbuf, g_conv);
    cudaGetSymbolAddress((void**)&ybuf,    g_y);
    cudaGetSymbolAddress((void**)&xtf,     g_xtf);
    cudaGetSymbolAddress((void**)&w1tf,    g_w1tf);
    cudaGetSymbolAddress((void**)&w2tf,    g_w2tf);

    cudaFuncSetAttribute(tf32_gemm_kernel,
                         cudaFuncAttributeMaxDynamicSharedMemorySize, GEMM_SMEM);
    cudaFuncSetAttribute(fused_scan_kernel,
                         cudaFuncAttributeMaxDynamicSharedMemorySize, SC_SMEM);

    static cudaStream_t sHi = nullptr;       // high-priority: conv + scan
    static cudaEvent_t evFork = nullptr, evScan = nullptr;
    if (sHi == nullptr) {
        int leastP = 0, greatestP = 0;
        cudaDeviceGetStreamPriorityRange(&leastP, &greatestP);
        cudaStreamCreateWithPriority(&sHi, cudaStreamNonBlocking, greatestP);
        cudaEventCreateWithFlags(&evFork, cudaEventDisableTiming);
        cudaEventCreateWithFlags(&evScan, cudaEventDisableTiming);
    }

    // 0) tf32 rounding: x and w1 (main stream)
    {
        long n4;
        n4 = (long)ROWS * DMODEL / 4;
        cvt_tf32_kernel<<<(unsigned)((n4 + 255) / 256), 256>>>(x, xtf, n4);
        n4 = (long)DMODEL * DINPROJ / 4;
        cvt_tf32_kernel<<<(unsigned)((n4 + 255) / 256), 256>>>(in_proj_w, w1tf, n4);
    }

    // 1) main stream: in_proj xBC+dt columns [2048, 4384) — full chip, alone
    {
        const int NB = DINPROJ - DINNER;          // 2336
        dim3 grid((NB + 127) / 128, ROWS / 128);  // 19 x 64
        tf32_gemm_kernel<<<grid, 256, GEMM_SMEM>>>(
            xtf, w1tf + DINNER, zxbcdt + DINNER, ROWS, NB, DMODEL,
            DINPROJ, DINPROJ);
    }
    cudaEventRecord(evFork, 0);

    // ---- HIGH-PRIORITY stream: conv + fused scan (gets SM placement first)
    cudaStreamWaitEvent(sHi, evFork, 0);
    {
        dim3 grid(CONVDIM / 256, ROWS / 8);
        conv_silu_kernel<<<grid, 256, 0, sHi>>>(zxbcdt, conv_w, conv_b, convbuf);
    }
    fused_scan_kernel<<<BATCH * NHEADS, 256, SC_SMEM, sHi>>>(
        convbuf, zxbcdt, dt_bias, A_log, Dparam, ybuf);
    cudaEventRecord(evScan, sHi);

    // ---- main (default-priority) stream: w2 cvt + z-columns GEMM, filling
    //      the SMs the scan leaves idle.
    {
        long n4 = (long)DINNER * DMODEL / 4;
        cvt_tf32_kernel<<<(unsigned)((n4 + 255) / 256), 256>>>(out_proj_w, w2tf, n4);
        dim3 grid(DINNER / 128, ROWS / 128);     // 16 x 64
        tf32_gemm_kernel<<<grid, 256, GEMM_SMEM>>>(
            xtf, w1tf, zxbcdt, ROWS, DINNER, DMODEL, DINPROJ, DINPROJ);
    }

    // join: rmsnorm needs y from the scan (z is in-order on main stream)
    cudaStreamWaitEvent(0, evScan, 0);

    // gated RMSNorm
    gated_rmsnorm_kernel<<<ROWS, 256>>>(ybuf, zxbcdt, norm_w);

    // out_proj
    {
        dim3 grid(DMODEL / 128, ROWS / 128);
        tf32_gemm_kernel<<<grid, 256, GEMM_SMEM>>>(
            ybuf, w2tf, out, ROWS, DMODEL, DINNER, DMODEL, DMODEL);
    }
}

// round 17
// speedup vs baseline: 1.1042x; 1.1042x over previous
#include <cuda_runtime.h>
#include <cuda_bf16.h>
#include <math.h>
#include <stdint.h>

// ---------------------------------------------------------------------------
// Problem constants (Mamba2 block)
// ---------------------------------------------------------------------------
#define BATCH     2
#define SEQLEN    4096
#define DMODEL    1024
#define DSTATE    128
#define DCONV     4
#define HEADDIM   64
#define DINNER    2048
#define NHEADS    32
#define CONVDIM   2304              // DINNER + 2*DSTATE
#define DINPROJ   4384              // 2*DINNER + 2*DSTATE + NHEADS
#define ROWS      (BATCH*SEQLEN)    // 8192
#define DTCOL     (2*DINNER + 2*DSTATE)   // 4352

#define T_CH      64
#define NCHUNK    (SEQLEN / T_CH)   // 64

// Scratch (allocation-free rule: __device__ globals)
__device__ float g_zxbcdt[(size_t)ROWS * DINPROJ];
__device__ float g_conv  [(size_t)ROWS * CONVDIM];   // tf32-rounded conv+silu
__device__ float g_y     [(size_t)ROWS * DINNER];
__device__ float g_xtf   [(size_t)ROWS * DMODEL];
__device__ float g_w1tf  [(size_t)DMODEL * DINPROJ];
__device__ float g_w2tf  [(size_t)DINNER * DMODEL];

__device__ __forceinline__ uint32_t f2tf32(float f) {
    uint32_t r;
    asm("cvt.rna.tf32.f32 %0, %1;" : "=r"(r) : "f"(f));
    return r;
}
__device__ __forceinline__ float tfr(float f) {
    return __uint_as_float(f2tf32(f));
}
__device__ __forceinline__ uint32_t smem_addr(const void* p) {
    return (uint32_t)__cvta_generic_to_shared(p);
}
__device__ __forceinline__ void cp16(uint32_t dst, const void* src, int sz) {
    asm volatile("cp.async.cg.shared.global [%0], [%1], 16, %2;"
                 :: "r"(dst), "l"(src), "r"(sz) : "memory");
}
__device__ __forceinline__ void cp4(uint32_t dst, const void* src) {
    asm volatile("cp.async.ca.shared.global [%0], [%1], 4;"
                 :: "r"(dst), "l"(src) : "memory");
}
#define CP_COMMIT() asm volatile("cp.async.commit_group;" ::: "memory")
#define CP_WAIT(n)  asm volatile("cp.async.wait_group %0;" :: "n"(n) : "memory")

#define MMA_TF32(acc, a0, a1, a2, a3, b0, b1)                               \
    asm volatile(                                                           \
        "mma.sync.aligned.m16n8k8.row.col.f32.tf32.tf32.f32 "               \
        "{%0,%1,%2,%3}, {%4,%5,%6,%7}, {%8,%9}, {%0,%1,%2,%3};"             \
        : "+f"((acc)[0]), "+f"((acc)[1]), "+f"((acc)[2]), "+f"((acc)[3])    \
        : "r"(a0), "r"(a1), "r"(a2), "r"(a3), "r"(b0), "r"(b1))

// ---------------------------------------------------------------------------
// Elementwise tf32 rounding pre-pass
// ---------------------------------------------------------------------------
__global__ void cvt_tf32_kernel(const float* __restrict__ in,
                                float* __restrict__ out, long n4)
{
    long i = (long)blockIdx.x * blockDim.x + threadIdx.x;
    if (i >= n4) return;
    float4 v = ((const float4*)in)[i];
    float4 o = make_float4(tfr(v.x), tfr(v.y), tfr(v.z), tfr(v.w));
    ((float4*)out)[i] = o;
}

// ---------------------------------------------------------------------------
// TF32 mma.sync GEMM, 3-stage cp.async pipeline (128x128 tile, 2 CTA/SM).
// C[r*ldC + c] = sum_k A[r*K + k] * B[k*ldB + c], c < Nb (guarded).
// ---------------------------------------------------------------------------
#define GSTAGES 3
#define ASTR 36
#define BSTR 136
#define STAGE_WORDS (128*ASTR + 32*BSTR)
#define GEMM_SMEM   (GSTAGES * STAGE_WORDS * 4)

__global__ __launch_bounds__(256, 2)
void tf32_gemm_kernel(const float* __restrict__ A, const float* __restrict__ B,
                      float* __restrict__ C, int M, int Nb, int K,
                      int ldB, int ldC)
{
    extern __shared__ uint32_t smem[];

    const int tid   = threadIdx.x;
    const int warp  = tid >> 5;
    const int lane  = tid & 31;
    const int g     = lane >> 2;
    const int t4    = lane & 3;
    const int warpM = warp >> 2;
    const int warpN = warp & 3;
    const int rowC  = blockIdx.y * 128;
    const int colC  = blockIdx.x * 128;
    const int NC    = K / 32;

    auto stage_cp = [&](int chunk, int slot) {
        uint32_t* As = smem + slot * STAGE_WORDS;
        uint32_t* Bs = As + 128 * ASTR;
        const int k0 = chunk * 32;
        #pragma unroll
        for (int p = 0; p < 4; p++) {
            int i = p * 256 + tid;
            int m = i >> 3, kq = i & 7;
            cp16(smem_addr(As + m * ASTR + kq * 4),
                 A + (size_t)(rowC + m) * K + k0 + kq * 4, 16);
        }
        #pragma unroll
        for (int p = 0; p < 4; p++) {
            int i = p * 256 + tid;
            int kl = i >> 5, nq = i & 31;
            int gcol = colC + nq * 4;
            int ok = (gcol < Nb);
            cp16(smem_addr(Bs + kl * BSTR + nq * 4),
                 B + (size_t)(k0 + kl) * ldB + (ok ? gcol : 0), ok ? 16 : 0);
        }
    };

    float acc[4][4][4];
    #pragma unroll
    for (int mi = 0; mi < 4; mi++)
        #pragma unroll
        for (int ni = 0; ni < 4; ni++)
            #pragma unroll
            for (int r = 0; r < 4; r++) acc[mi][ni][r] = 0.f;

    stage_cp(0, 0); CP_COMMIT();
    stage_cp(1, 1); CP_COMMIT();

    for (int i = 0; i < NC; i++) {
        if (i < NC - 1) CP_WAIT(1); else CP_WAIT(0);
        __syncthreads();
        if (i + 2 < NC) { stage_cp(i + 2, (i + 2) % GSTAGES); CP_COMMIT(); }

        const uint32_t* As = smem + (i % GSTAGES) * STAGE_WORDS;
        const uint32_t* Bs = As + 128 * ASTR;

        #pragma unroll
        for (int ks = 0; ks < 4; ks++) {
            const int kk = ks * 8;
            uint32_t af[4][4];
            #pragma unroll
            for (int mi = 0; mi < 4; mi++) {
                int m = warpM * 64 + mi * 16;
                af[mi][0] = As[(m + g)     * ASTR + kk + t4];
                af[mi][1] = As[(m + g + 8) * ASTR + kk + t4];
                af[mi][2] = As[(m + g)     * ASTR + kk + t4 + 4];
                af[mi][3] = As[(m + g + 8) * ASTR + kk + t4 + 4];
            }
            uint32_t bf[4][2];
            #pragma unroll
            for (int ni = 0; ni < 4; ni++) {
                int n = warpN * 32 + ni * 8 + g;
                bf[ni][0] = Bs[(kk + t4)     * BSTR + n];
                bf[ni][1] = Bs[(kk + t4 + 4) * BSTR + n];
            }
            #pragma unroll
            for (int mi = 0; mi < 4; mi++)
                #pragma unroll
                for (int ni = 0; ni < 4; ni++)
                    MMA_TF32(acc[mi][ni], af[mi][0], af[mi][1], af[mi][2],
                             af[mi][3], bf[ni][0], bf[ni][1]);
        }
    }

    #pragma unroll
    for (int mi = 0; mi < 4; mi++) {
        int r0 = rowC + warpM * 64 + mi * 16 + g;
        #pragma unroll
        for (int ni = 0; ni < 4; ni++) {
            int cc = colC + warpN * 32 + ni * 8 + t4 * 2;
            if (cc < Nb) {
                *(float2*)(C + (size_t)r0 * ldC + cc)       =
                    make_float2(acc[mi][ni][0], acc[mi][ni][1]);
                *(float2*)(C + (size_t)(r0 + 8) * ldC + cc) =
                    make_float2(acc[mi][ni][2], acc[mi][ni][3]);
            }
        }
    }
}

// ---------------------------------------------------------------------------
// Causal depthwise conv1d (K=4) + SiLU, sliding-window, 8 timesteps/thread.
// ---------------------------------------------------------------------------
__global__ __launch_bounds__(256)
void conv_silu_kernel(const float* __restrict__ zxbcdt,
                      const float* __restrict__ conv_w,
                      const float* __restrict__ conv_b,
                      float* __restrict__ out)
{
    const int  c  = blockIdx.x * 256 + threadIdx.x;
    const long r0 = (long)blockIdx.y * 8;
    const int  l0 = (int)(r0 & (SEQLEN - 1));

    const float w0 = conv_w[0 * CONVDIM + c];
    const float w1 = conv_w[1 * CONVDIM + c];
    const float w2 = conv_w[2 * CONVDIM + c];
    const float w3 = conv_w[3 * CONVDIM + c];
    const float bias = conv_b[c];

    const float* base = zxbcdt + r0 * DINPROJ + DINNER + c;
    float xm3 = 0.f, xm2 = 0.f, xm1 = 0.f;
    if (l0 > 0) {
        xm3 = base[-3 * (long)DINPROJ];
        xm2 = base[-2 * (long)DINPROJ];
        xm1 = base[-1 * (long)DINPROJ];
    }
    float* orow = out + r0 * CONVDIM + c;
    #pragma unroll
    for (int i = 0; i < 8; i++) {
        float x0 = base[(long)i * DINPROJ];
        float acc = bias + w0 * x0 + w1 * xm1 + w2 * xm2 + w3 * xm3;
        float s = acc / (1.f + __expf(-acc));
        orow[(long)i * CONVDIM] = tfr(s);
        xm3 = xm2; xm2 = xm1; xm1 = x0;
    }
}

// ---------------------------------------------------------------------------
// FUSED chunked scan, p-split: 2 CTAs per (b,h) -> 128 CTAs.
// Each CTA owns 32 head-dim rows; state = [32][128] in 16 regs/thread.
// Gram C.B^T computed redundantly in both halves (identical values).
// Smem 198,176 B: 2 stages x [B 64x132 | C 64x132 | X 64x36 | dt 64]
//                 + Ss[32x132] + Ms[64x68] + Xw[32x68] + weights.
// ---------------------------------------------------------------------------
#define SC_STG   (8448 + 8448 + 2304 + 64)          // 19264 words/stage
#define SC_WORDS (2*SC_STG + 4224 + 4352 + 2176 + 4*64 + 8)   // 49544
#define SC_SMEM  (SC_WORDS * 4)                      // 198,176 B

__global__ __launch_bounds__(256, 1)
void fused_scan_kernel(const float* __restrict__ convout,
                       const float* __restrict__ zxbcdt,
                       const float* __restrict__ dt_bias,
                       const float* __restrict__ A_log,
                       const float* __restrict__ Dparam,
                       float* __restrict__ y)
{
    extern __shared__ float sm[];

    const int bh  = blockIdx.x >> 1;
    const int ph  = blockIdx.x & 1;      // p-half: rows [ph*32, ph*32+32)
    const int b   = bh >> 5;
    const int h   = bh & 31;
    const int pbase = ph * 32;
    const long rb = (long)b * SEQLEN;
    const int tid  = threadIdx.x;
    const int warp = tid >> 5;
    const int lane = tid & 31;
    const int g    = lane >> 2;
    const int t4   = lane & 3;
    const int wM   = warp >> 2;          // 0..1
    const int wN   = warp & 3;           // 0..3

    const float A   = -__expf(A_log[h]);
    const float Dh  = Dparam[h];
    const float dtb = dt_bias[h];

    float* Ss   = sm + 2 * SC_STG;       // state [p=32][n], stride 132
    float* Ms   = Ss + 4224;             // masked gram [t][s], stride 68
    float* Xw   = Ms + 4352;             // weighted x^T [p=32][t], stride 68
    float* wrow = Xw + 2176;
    float* wcol = wrow + 64;
    float* swS  = wcol + 64;
    float* set  = swS + 64;
    float* scd  = set + 64;

    auto stage = [&](int k, int s) {
        float* Bs  = sm + s * SC_STG;
        float* Cs  = Bs + 8448;
        float* Xs  = Cs + 8448;          // [t][p_local], stride 36
        float* dtr = Xs + 2304;
        const long r0 = rb + (long)k * T_CH;
        #pragma unroll
        for (int j = 0; j < 8; j++) {
            int idx = j * 256 + tid;
            int t = idx >> 5, q = idx & 31;
            const float* row = convout + (r0 + t) * CONVDIM;
            cp16(smem_addr(Bs + t * 132 + q * 4), row + DINNER + q * 4, 16);
            cp16(smem_addr(Cs + t * 132 + q * 4), row + DINNER + DSTATE + q * 4, 16);
        }
        #pragma unroll
        for (int j = 0; j < 2; j++) {
            int idx = j * 256 + tid;
            int t = idx >> 3, q = idx & 7;
            cp16(smem_addr(Xs + t * 36 + q * 4),
                 convout + (r0 + t) * CONVDIM + h * HEADDIM + pbase + q * 4, 16);
        }
        if (tid < 64)
            cp4(smem_addr(dtr + tid), zxbcdt + (r0 + tid) * DINPROJ + DTCOL + h);
    };

    // Persistent state [p=32][n=128]: row tile = wM*16, col tile = wN*32.
    float stacc[4][4];
    #pragma unroll
    for (int ni = 0; ni < 4; ni++)
        #pragma unroll
        for (int r = 0; r < 4; r++) stacc[ni][r] = 0.f;

    stage(0, 0); CP_COMMIT();

    for (int k = 0; k < NCHUNK; k++) {
        const int s = k & 1;
        if (k + 1 < NCHUNK) { stage(k + 1, s ^ 1); CP_COMMIT(); }

        float* Bs  = sm + s * SC_STG;
        float* Cs  = Bs + 8448;
        float* Xs  = Cs + 8448;
        float* dtr = Xs + 2304;
        const long r0 = rb + (long)k * T_CH;

        // ---- spill state -> Ss
        {
            int pb = wM * 16;
            #pragma unroll
            for (int ni = 0; ni < 4; ni++) {
                int nb = wN * 32 + ni * 8 + 2 * t4;
                Ss[(pb + g)     * 132 + nb]     = tfr(stacc[ni][0]);
                Ss[(pb + g)     * 132 + nb + 1] = tfr(stacc[ni][1]);
                Ss[(pb + g + 8) * 132 + nb]     = tfr(stacc[ni][2]);
                Ss[(pb + g + 8) * 132 + nb + 1] = tfr(stacc[ni][3]);
            }
        }

        if (k + 1 < NCHUNK) CP_WAIT(1); else CP_WAIT(0);
        __syncthreads();                 // stage k + Ss visible

        // ---- dt softplus + warp-shuffle cumsum + weights (warp 0)
        if (warp == 0) {
            float rv0 = dtr[lane] + dtb;
            float rv1 = dtr[lane + 32] + dtb;
            float d0 = (rv0 > 20.f) ? rv0 : log1pf(__expf(rv0));
            float d1 = (rv1 > 20.f) ? rv1 : log1pf(__expf(rv1));
            float v0 = d0, v1 = d1;
            #pragma unroll
            for (int off = 1; off < 32; off <<= 1) {
                float u0 = __shfl_up_sync(0xffffffffu, v0, off);
                float u1 = __shfl_up_sync(0xffffffffu, v1, off);
                if (lane >= off) { v0 += u0; v1 += u1; }
            }
            float tot0 = __shfl_sync(0xffffffffu, v0, 31);
            v1 += tot0;
            float ST   = __shfl_sync(0xffffffffu, v1, 31);
            float Smid = tot0;
            wrow[lane]      = __expf(A * (v0 - Smid));
            wrow[lane + 32] = __expf(A * (v1 - Smid));
            wcol[lane]      = d0 * __expf(-A * (v0 - Smid));
            wcol[lane + 32] = d1 * __expf(-A * (v1 - Smid));
            swS[lane]       = d0 * __expf(A * (ST - v0));
            swS[lane + 32]  = d1 * __expf(A * (ST - v1));
            set[lane]       = __expf(A * v0);
            set[lane + 32]  = __expf(A * v1);
            if (lane == 0) scd[0] = __expf(A * ST);
        }
        __syncthreads();
        const float cd = scd[0];

        // ---- merged (shared C fragments, K = n = 128):
        //      accs[t][pl=32] = C . S0^T   (cols: wN*8)
        //      accg[t][s=64]  = C . B^T    (cols: wN*16 + ni*8)
        float accs[2][4], accg[2][2][4];
        #pragma unroll
        for (int mi = 0; mi < 2; mi++) {
            #pragma unroll
            for (int r = 0; r < 4; r++) accs[mi][r] = 0.f;
            #pragma unroll
            for (int ni = 0; ni < 2; ni++)
                #pragma unroll
                for (int r = 0; r < 4; r++) accg[mi][ni][r] = 0.f;
        }

        #pragma unroll
        for (int ks = 0; ks < 16; ks++) {
            const int kk = ks * 8;
            uint32_t af[2][4], bfS[2], bfB[2][2];
            #pragma unroll
            for (int mi = 0; mi < 2; mi++) {
                int m = wM * 32 + mi * 16;
                af[mi][0] = __float_as_uint(Cs[(m + g)     * 132 + kk + t4]);
                af[mi][1] = __float_as_uint(Cs[(m + g + 8) * 132 + kk + t4]);
                af[mi][2] = __float_as_uint(Cs[(m + g)     * 132 + kk + t4 + 4]);
                af[mi][3] = __float_as_uint(Cs[(m + g + 8) * 132 + kk + t4 + 4]);
            }
            {
                int p = wN * 8 + g;
                bfS[0] = __float_as_uint(Ss[p * 132 + kk + t4]);
                bfS[1] = __float_as_uint(Ss[p * 132 + kk + t4 + 4]);
            }
            #pragma unroll
            for (int ni = 0; ni < 2; ni++) {
                int ss = wN * 16 + ni * 8 + g;
                bfB[ni][0] = __float_as_uint(Bs[ss * 132 + kk + t4]);
                bfB[ni][1] = __float_as_uint(Bs[ss * 132 + kk + t4 + 4]);
            }
            #pragma unroll
            for (int mi = 0; mi < 2; mi++) {
                MMA_TF32(accs[mi], af[mi][0], af[mi][1], af[mi][2],
                         af[mi][3], bfS[0], bfS[1]);
                #pragma unroll
                for (int ni = 0; ni < 2; ni++)
                    MMA_TF32(accg[mi][ni], af[mi][0], af[mi][1], af[mi][2],
                             af[mi][3], bfB[ni][0], bfB[ni][1]);
            }
        }
        __syncthreads();                 // all Cs/Ss reads done

        // ---- mask -> Ms (outer-product weights); Xw[p][t] = swS_t * x[t][p]
        #pragma unroll
        for (int mi = 0; mi < 2; mi++) {
            #pragma unroll
            for (int ni = 0; ni < 2; ni++) {
                int tb = wM * 32 + mi * 16;
                int sb = wN * 16 + ni * 8 + 2 * t4;
                #pragma unroll
                for (int r = 0; r < 4; r++) {
                    int tt = tb + g + ((r >= 2) ? 8 : 0);
                    int ss = sb + (r & 1);
                    float w = (ss <= tt) ? wrow[tt] * wcol[ss] : 0.f;
                    Ms[tt * 68 + ss] = tfr(accg[mi][ni][r] * w);
                }
            }
        }
        #pragma unroll
        for (int j = 0; j < 8; j++) {
            int idx = j * 256 + tid;
            int p = idx >> 6, t = idx & 63;     // p in 0..31
            Xw[p * 68 + t] = tfr(swS[t] * Xs[t * 36 + p]);
        }
        __syncthreads();                 // Ms + Xw ready

        // ---- acc_y[t][pl=32] = M . X (K = s = 64)
        float acc2[2][4];
        #pragma unroll
        for (int mi = 0; mi < 2; mi++)
            #pragma unroll
            for (int r = 0; r < 4; r++) acc2[mi][r] = 0.f;

        #pragma unroll
        for (int ks = 0; ks < 8; ks++) {
            const int kk = ks * 8;
            uint32_t af[2][4], bf[2];
            #pragma unroll
            for (int mi = 0; mi < 2; mi++) {
                int m = wM * 32 + mi * 16;
                af[mi][0] = __float_as_uint(Ms[(m + g)     * 68 + kk + t4]);
                af[mi][1] = __float_as_uint(Ms[(m + g + 8) * 68 + kk + t4]);
                af[mi][2] = __float_as_uint(Ms[(m + g)     * 68 + kk + t4 + 4]);
                af[mi][3] = __float_as_uint(Ms[(m + g + 8) * 68 + kk + t4 + 4]);
            }
            {
                int p = wN * 8 + g;
                bf[0] = __float_as_uint(Xs[(kk + t4)     * 36 + p]);
                bf[1] = __float_as_uint(Xs[(kk + t4 + 4) * 36 + p]);
            }
            #pragma unroll
            for (int mi = 0; mi < 2; mi++)
                MMA_TF32(acc2[mi], af[mi][0], af[mi][1], af[mi][2],
                         af[mi][3], bf[0], bf[1]);
        }

        // ---- epilogue: y = Y_intra + et*(C.S0) + D*x (single write)
        #pragma unroll
        for (int mi = 0; mi < 2; mi++) {
            int tb = wM * 32 + mi * 16;
            int pl = wN * 8 + 2 * t4;           // local p col
            int t0 = tb + g, t1 = tb + g + 8;
            float e0 = set[t0], e1 = set[t1];
            int gcol = h * HEADDIM + pbase + pl;
            float2 o0 = make_float2(
                acc2[mi][0] + e0 * accs[mi][0] + Dh * Xs[t0 * 36 + pl],
                acc2[mi][1] + e0 * accs[mi][1] + Dh * Xs[t0 * 36 + pl + 1]);
            float2 o1 = make_float2(
                acc2[mi][2] + e1 * accs[mi][2] + Dh * Xs[t1 * 36 + pl],
                acc2[mi][3] + e1 * accs[mi][3] + Dh * Xs[t1 * 36 + pl + 1]);
            *(float2*)(y + (r0 + t0) * DINNER + gcol) = o0;
            *(float2*)(y + (r0 + t1) * DINNER + gcol) = o1;
        }

        // ---- state update: stacc = cd*stacc + Xw . B (K = t = 64)
        #pragma unroll
        for (int ni = 0; ni < 4; ni++)
            #pragma unroll
            for (int r = 0; r < 4; r++) stacc[ni][r] *= cd;

        #pragma unroll
        for (int ks = 0; ks < 8; ks++) {
            const int kk = ks * 8;
            uint32_t af[4], bf[4][2];
            {
                int p = wM * 16;
                af[0] = __float_as_uint(Xw[(p + g)     * 68 + kk + t4]);
                af[1] = __float_as_uint(Xw[(p + g + 8) * 68 + kk + t4]);
                af[2] = __float_as_uint(Xw[(p + g)     * 68 + kk + t4 + 4]);
                af[3] = __float_as_uint(Xw[(p + g + 8) * 68 + kk + t4 + 4]);
            }
            #pragma unroll
            for (int ni = 0; ni < 4; ni++) {
                int n = wN * 32 + ni * 8 + g;
                bf[ni][0] = __float_as_uint(Bs[(kk + t4)     * 132 + n]);
                bf[ni][1] = __float_as_uint(Bs[(kk + t4 + 4) * 132 + n]);
            }
            #pragma unroll
            for (int ni = 0; ni < 4; ni++)
                MMA_TF32(stacc[ni], af[0], af[1], af[2], af[3],
                         bf[ni][0], bf[ni][1]);
        }
        __syncthreads();   // buf s reads done before re-stage
    }
}

// ---------------------------------------------------------------------------
// Gated RMSNorm in place on y; output tf32-rounded.
// ---------------------------------------------------------------------------
__global__ __launch_bounds__(256)
void gated_rmsnorm_kernel(float* __restrict__ y,
                          const float* __restrict__ zxbcdt,
                          const float* __restrict__ norm_w)
{
    long r = blockIdx.x;
    int tid = threadIdx.x;
    float* yr = y + r * DINNER;
    const float* zr = zxbcdt + r * DINPROJ;

    float vals[8];
    float ss = 0.f;
    #pragma unroll
    for (int i = 0; i < 8; i++) {
        int c = tid + i * 256;
        float z  = zr[c];
        float gv = yr[c] * (z / (1.f + __expf(-z)));
        vals[i] = gv;
        ss = fmaf(gv, gv, ss);
    }

    __shared__ float sred[256];
    sred[tid] = ss;
    __syncthreads();
    #pragma unroll
    for (int off = 128; off > 0; off >>= 1) {
        if (tid < off) sred[tid] += sred[tid + off];
        __syncthreads();
    }
    float scale = rsqrtf(sred[0] / (float)DINNER + 1e-5f);

    #pragma unroll
    for (int i = 0; i < 8; i++) {
        int c = tid + i * 256;
        yr[c] = tfr(vals[i] * scale * norm_w[c]);
    }
}

// ---------------------------------------------------------------------------
// Launch. Inputs: x, in_proj_w, conv_w, conv_b, norm_w, out_proj_w,
//                 dt_bias, A_log, D
// Schedule: R14's known-good fork (z-GEMM + w2 cvt on side stream, forked
// right after the x/w1 cvt; join before rmsnorm).
// ---------------------------------------------------------------------------
extern "C" void kernel_launch(void* const* d_in, const int* in_sizes, int n_in,
                              void* d_out, int out_size)
{
    const float* x          = (const float*)d_in[0];
    const float* in_proj_w  = (const float*)d_in[1];
    const float* conv_w     = (const float*)d_in[2];
    const float* conv_b     = (const float*)d_in[3];
    const float* norm_w     = (const float*)d_in[4];
    const float* out_proj_w = (const float*)d_in[5];
    const float* dt_bias    = (const float*)d_in[6];
    const float* A_log      = (const float*)d_in[7];
    const float* Dparam     = (const float*)d_in[8];
    float* out = (float*)d_out;

    float *zxbcdt, *convbuf, *ybuf, *xtf, *w1tf, *w2tf;
    cudaGetSymbolAddress((void**)&zxbcdt,  g_zxbcdt);
    cudaGetSymbolAddress((void**)&convbuf, g_conv);
    cudaGetSymbolAddress((void**)&ybuf,    g_y);
    cudaGetSymbolAddress((void**)&xtf,     g_xtf);
    cudaGetSymbolAddress((void**)&w1tf,    g_w1tf);
    cudaGetSymbolAddress((void**)&w2tf,    g_w2tf);

    cudaFuncSetAttribute(tf32_gemm_kernel,
                         cudaFuncAttributeMaxDynamicSharedMemorySize, GEMM_SMEM);
    cudaFuncSetAttribute(fused_scan_kernel,
                         cudaFuncAttributeMaxDynamicSharedMemorySize, SC_SMEM);

    static cudaStream_t s1 = nullptr;
    static cudaEvent_t evFork = nullptr, evJoin = nullptr;
    if (s1 == nullptr) {
        cudaStreamCreateWithFlags(&s1, cudaStreamNonBlocking);
        cudaEventCreateWithFlags(&evFork, cudaEventDisableTiming);
        cudaEventCreateWithFlags(&evJoin, cudaEventDisableTiming);
    }

    // 0) tf32 rounding: x and w1
    {
        long n4;
        n4 = (long)ROWS * DMODEL / 4;
        cvt_tf32_kernel<<<(unsigned)((n4 + 255) / 256), 256>>>(x, xtf, n4);
        n4 = (long)DMODEL * DINPROJ / 4;
        cvt_tf32_kernel<<<(unsigned)((n4 + 255) / 256), 256>>>(in_proj_w, w1tf, n4);
    }

    // Fork side stream (depends on xtf/w1tf just produced)
    cudaEventRecord(evFork, 0);
    cudaStreamWaitEvent(s1, evFork, 0);

    // ---- side stream: w2 cvt + in_proj z-columns [0, 2048)
    {
        long n4 = (long)DINNER * DMODEL / 4;
        cvt_tf32_kernel<<<(unsigned)((n4 + 255) / 256), 256, 0, s1>>>(
            out_proj_w, w2tf, n4);
        dim3 grid(DINNER / 128, ROWS / 128);     // 16 x 64
        tf32_gemm_kernel<<<grid, 256, GEMM_SMEM, s1>>>(
            xtf, w1tf, zxbcdt, ROWS, DINNER, DMODEL, DINPROJ, DINPROJ);
    }
    cudaEventRecord(evJoin, s1);

    // ---- main stream: in_proj xBC+dt columns [2048, 4384)
    {
        const int NB = DINPROJ - DINNER;          // 2336
        dim3 grid((NB + 127) / 128, ROWS / 128);  // 19 x 64
        tf32_gemm_kernel<<<grid, 256, GEMM_SMEM>>>(
            xtf, w1tf + DINNER, zxbcdt + DINNER, ROWS, NB, DMODEL,
            DINPROJ, DINPROJ);
    }

    // conv + silu (reads cols [2048, 4352))
    {
        dim3 grid(CONVDIM / 256, ROWS / 8);
        conv_silu_kernel<<<grid, 256>>>(zxbcdt, conv_w, conv_b, convbuf);
    }

    // fused chunked scan, p-split: 128 CTAs
    fused_scan_kernel<<<BATCH * NHEADS * 2, 256, SC_SMEM>>>(
        convbuf, zxbcdt, dt_bias, A_log, Dparam, ybuf);

    // join: rmsnorm needs z columns from the side stream
    cudaStreamWaitEvent(0, evJoin, 0);

    // gated RMSNorm
    gated_rmsnorm_kernel<<<ROWS, 256>>>(ybuf, zxbcdt, norm_w);

    // out_proj
    {
        dim3 grid(DMODEL / 128, ROWS / 128);
        tf32_gemm_kernel<<<grid, 256, GEMM_SMEM>>>(
            ybuf, w2tf, out, ROWS, DMODEL, DINNER, DMODEL, DMODEL);
    }
}